// round 8
// baseline (speedup 1.0000x reference)
#include <cuda_runtime.h>
#include <cstdint>

// fastmax attention, b=4 h=16 n=1024 d=64.
// Round 7: ALU-free mma streams (global pre-split Q/K/V, epilogue-split S),
// split accumulators for ILP, j-indexed bias table with float2 gather,
// causal block skipping.

#define B_  4
#define H_  16
#define N_  1024
#define D_  64
#define BH_ (B_*H_)

__device__ float g_qnh[(size_t)BH_ * N_ * D_];          // tf32-hi of q/||q||
__device__ float g_qnl[(size_t)BH_ * N_ * D_];          // tf32-lo
__device__ float g_knh[(size_t)BH_ * N_ * D_];          // tf32-hi of k/||k||
__device__ float g_knl[(size_t)BH_ * N_ * D_];          // tf32-lo
__device__ float g_vph[(size_t)BH_ * N_ * D_];          // tf32-hi of v+0.1*noise
__device__ float g_vpl[(size_t)BH_ * N_ * D_];          // tf32-lo
__device__ float g_qr [(size_t)BH_ * N_ * N_];          // bias[i][j] = q_i.rpe2[i-j]

// ---------------------------------------------------------------------------
__device__ __forceinline__ void split2(float x, uint32_t& hi, uint32_t& lo) {
    asm("cvt.rna.tf32.f32 %0, %1;" : "=r"(hi) : "f"(x));
    float r = x - __uint_as_float(hi);
    asm("cvt.rna.tf32.f32 %0, %1;" : "=r"(lo) : "f"(r));
}

__device__ __forceinline__ void mma_tf32(float c[4], const uint32_t a[4],
                                         uint32_t b0, uint32_t b1) {
    asm("mma.sync.aligned.m16n8k8.row.col.f32.tf32.tf32.f32 "
        "{%0,%1,%2,%3}, {%4,%5,%6,%7}, {%8,%9}, {%0,%1,%2,%3};"
        : "+f"(c[0]), "+f"(c[1]), "+f"(c[2]), "+f"(c[3])
        : "r"(a[0]), "r"(a[1]), "r"(a[2]), "r"(a[3]), "r"(b0), "r"(b1));
}

__device__ __forceinline__ void cp_async16(void* sdst, const void* gsrc) {
    uint32_t s = (uint32_t)__cvta_generic_to_shared(sdst);
    asm volatile("cp.async.cg.shared.global [%0], [%1], 16;" :: "r"(s), "l"(gsrc));
}

// ---------------------------------------------------------------------------
// prep: normalize q,k and split to tf32 hi/lo (one warp per 64-float row)
// ---------------------------------------------------------------------------
__global__ void prep_norm_kernel(const float* __restrict__ q,
                                 const float* __restrict__ k) {
    int gw   = (blockIdx.x * blockDim.x + threadIdx.x) >> 5;
    int lane = threadIdx.x & 31;
    const int total = BH_ * N_;
    const bool is_q = (gw < total);
    const int row = is_q ? gw : gw - total;
    const float* src = is_q ? q : k;
    const float2 v = reinterpret_cast<const float2*>(src + (size_t)row * D_)[lane];
    float ss = v.x * v.x + v.y * v.y;
    #pragma unroll
    for (int o = 16; o > 0; o >>= 1) ss += __shfl_xor_sync(0xffffffffu, ss, o);
    float inv = rsqrtf(ss);
    uint32_t xh, xl, yh, yl;
    split2(v.x * inv, xh, xl);
    split2(v.y * inv, yh, yl);
    float* dh = is_q ? g_qnh : g_knh;
    float* dl = is_q ? g_qnl : g_knl;
    reinterpret_cast<float2*>(dh + (size_t)row * D_)[lane] =
        make_float2(__uint_as_float(xh), __uint_as_float(yh));
    reinterpret_cast<float2*>(dl + (size_t)row * D_)[lane] =
        make_float2(__uint_as_float(xl), __uint_as_float(yl));
}

// ---------------------------------------------------------------------------
// prep: Vp = v + 0.1*noise -> split tf32 hi/lo
// ---------------------------------------------------------------------------
__global__ void prep_v_kernel(const float* __restrict__ v,
                              const float* __restrict__ nz) {
    int i = blockIdx.x * blockDim.x + threadIdx.x;
    float4 a = reinterpret_cast<const float4*>(v)[i];
    float4 b = reinterpret_cast<const float4*>(nz)[i];
    float4 h, l;
    uint32_t th, tl;
    split2(fmaf(0.1f, b.x, a.x), th, tl); h.x = __uint_as_float(th); l.x = __uint_as_float(tl);
    split2(fmaf(0.1f, b.y, a.y), th, tl); h.y = __uint_as_float(th); l.y = __uint_as_float(tl);
    split2(fmaf(0.1f, b.z, a.z), th, tl); h.z = __uint_as_float(th); l.z = __uint_as_float(tl);
    split2(fmaf(0.1f, b.w, a.w), th, tl); h.w = __uint_as_float(th); l.w = __uint_as_float(tl);
    reinterpret_cast<float4*>(g_vph)[i] = h;
    reinterpret_cast<float4*>(g_vpl)[i] = l;
}

// ---------------------------------------------------------------------------
// bias[i][j] = Qn_i . rpe2[i-j] for j<=i, via 3xTF32 mma on (i,m) tiles,
// stored j-indexed. block = 8 warps, warp w owns rows w*16..w*16+15.
// ---------------------------------------------------------------------------
__global__ void __launch_bounds__(256) qr_mma_kernel(const float* __restrict__ rpe) {
    const int mx = blockIdx.x, iy = blockIdx.y, bh = blockIdx.z;
    if (mx > 2 * iy + 1) return;

    extern __shared__ float sm[];
    float* Qsh = sm;                 // [128][68]
    float* Qsl = sm + 8704;          // [128][68]
    float* Rsh = sm + 17408;         // [64][68]
    float* Rsl = sm + 21760;         // [64][68]

    const int tid = threadIdx.x;
    const int w = tid >> 5, lane = tid & 31;
    const int g = lane >> 2, l = lane & 3;
    const int i0 = iy * 128, m0 = mx * 64;

    const float* qh = g_qnh + ((size_t)bh * N_ + i0) * D_;
    const float* ql = g_qnl + ((size_t)bh * N_ + i0) * D_;
    #pragma unroll
    for (int e = tid; e < 2048; e += 256) {
        int r = e >> 4, c = (e & 15) << 2;
        *reinterpret_cast<float4*>(Qsh + r * 68 + c) =
            *reinterpret_cast<const float4*>(qh + r * 64 + c);
        *reinterpret_cast<float4*>(Qsl + r * 68 + c) =
            *reinterpret_cast<const float4*>(ql + r * 64 + c);
    }
    const float* rsrc = rpe + (size_t)(N_ - 1 + m0) * D_;
    #pragma unroll
    for (int e = tid; e < 1024; e += 256) {
        int r = e >> 4, c = (e & 15) << 2;
        float4 x = *reinterpret_cast<const float4*>(rsrc + r * 64 + c);
        float4 hh, ll;
        uint32_t th, tl;
        split2(x.x, th, tl); hh.x = __uint_as_float(th); ll.x = __uint_as_float(tl);
        split2(x.y, th, tl); hh.y = __uint_as_float(th); ll.y = __uint_as_float(tl);
        split2(x.z, th, tl); hh.z = __uint_as_float(th); ll.z = __uint_as_float(tl);
        split2(x.w, th, tl); hh.w = __uint_as_float(th); ll.w = __uint_as_float(tl);
        *reinterpret_cast<float4*>(Rsh + r * 68 + c) = hh;
        *reinterpret_cast<float4*>(Rsl + r * 68 + c) = ll;
    }
    __syncthreads();

    const int r0 = w * 16 + g;
    const int i_lo = i0 + r0, i_hi = i_lo + 8;
    // skip n-blocks fully above the needed band (m > i for all 16 rows)
    const int n_lim = max(0, min(8, ((i_hi - m0) >> 3) + 1));

    uint32_t qah[8][4], qal[8][4];
    #pragma unroll
    for (int kk = 0; kk < 8; kk++) {
        qah[kk][0] = __float_as_uint(Qsh[r0 * 68 + kk * 8 + l]);
        qah[kk][1] = __float_as_uint(Qsh[(r0 + 8) * 68 + kk * 8 + l]);
        qah[kk][2] = __float_as_uint(Qsh[r0 * 68 + kk * 8 + l + 4]);
        qah[kk][3] = __float_as_uint(Qsh[(r0 + 8) * 68 + kk * 8 + l + 4]);
        qal[kk][0] = __float_as_uint(Qsl[r0 * 68 + kk * 8 + l]);
        qal[kk][1] = __float_as_uint(Qsl[(r0 + 8) * 68 + kk * 8 + l]);
        qal[kk][2] = __float_as_uint(Qsl[r0 * 68 + kk * 8 + l + 4]);
        qal[kk][3] = __float_as_uint(Qsl[(r0 + 8) * 68 + kk * 8 + l + 4]);
    }

    float acc[8][4] = {}, ac2[8][4] = {};
    #pragma unroll
    for (int kk = 0; kk < 8; kk++)
        #pragma unroll
        for (int n = 0; n < 8; n++) {
            if (n < n_lim) {
                const int o0 = (n * 8 + g) * 68 + kk * 8 + l;
                uint32_t bh0 = __float_as_uint(Rsh[o0]);
                uint32_t bh1 = __float_as_uint(Rsh[o0 + 4]);
                uint32_t bl0 = __float_as_uint(Rsl[o0]);
                uint32_t bl1 = __float_as_uint(Rsl[o0 + 4]);
                mma_tf32(acc[n], qah[kk], bh0, bh1);
                mma_tf32(ac2[n], qal[kk], bh0, bh1);
                mma_tf32(ac2[n], qah[kk], bl0, bl1);
            }
        }

    // store j-indexed: bias[i][i-m]
    float* dlo = g_qr + (size_t)bh * N_ * N_ + (size_t)i_lo * N_ + i_lo;
    float* dhi = g_qr + (size_t)bh * N_ * N_ + (size_t)i_hi * N_ + i_hi;
    #pragma unroll
    for (int n = 0; n < 8; n++) {
        if (n < n_lim) {
            int mc = m0 + n * 8 + 2 * l;
            float s00 = acc[n][0] + ac2[n][0];
            float s01 = acc[n][1] + ac2[n][1];
            float s10 = acc[n][2] + ac2[n][2];
            float s11 = acc[n][3] + ac2[n][3];
            if (mc     <= i_lo) dlo[-mc]     = s00;
            if (mc + 1 <= i_lo) dlo[-mc - 1] = s01;
            if (mc     <= i_hi) dhi[-mc]     = s10;
            if (mc + 1 <= i_hi) dhi[-mc - 1] = s11;
        }
    }
}

// ---------------------------------------------------------------------------
// Main fused attention: block = (bh, 128-row i-tile), 8 warps.
// ---------------------------------------------------------------------------
__global__ void __launch_bounds__(256) fastmax_mma_kernel(float* __restrict__ out) {
    extern __shared__ float sm[];
    float* Qsh = sm;                 // [128][68], reused as Ssh
    float* Qsl = sm + 8704;          // [128][68], reused as Ssl
    float* Khs = sm + 17408;         // 2 x [64][68]
    float* Kls = sm + 26112;         // 2 x [64][68]
    float* Vhs = sm + 34816;         // 2 x [64][72]
    float* Vls = sm + 44032;         // 2 x [64][72]

    const int it = 7 - blockIdx.x;   // heavy tiles first
    const int bh = blockIdx.y;
    const int i0 = it * 128;

    const int tid = threadIdx.x;
    const int w = tid >> 5, lane = tid & 31;
    const int g = lane >> 2, l = lane & 3;
    const int r0 = w * 16 + g;

    auto load_tile_async = [&](int j0, int buf) {
        const size_t base = ((size_t)bh * N_ + j0) * D_;
        const float* kh = g_knh + base;
        const float* kl = g_knl + base;
        const float* vh = g_vph + base;
        const float* vl = g_vpl + base;
        float* Kh = Khs + buf * 4352;
        float* Kl = Kls + buf * 4352;
        float* Vh = Vhs + buf * 4608;
        float* Vl = Vls + buf * 4608;
        #pragma unroll
        for (int e = tid; e < 1024; e += 256) {
            int r = e >> 4, c = (e & 15) << 2;
            cp_async16(Kh + r * 68 + c, kh + r * 64 + c);
            cp_async16(Kl + r * 68 + c, kl + r * 64 + c);
            cp_async16(Vh + r * 72 + c, vh + r * 64 + c);
            cp_async16(Vl + r * 72 + c, vl + r * 64 + c);
        }
    };

    // kick off K/V tile 0, then stage Q hi/lo
    load_tile_async(0, 0);
    asm volatile("cp.async.commit_group;");

    const float* qh = g_qnh + ((size_t)bh * N_ + i0) * D_;
    const float* ql = g_qnl + ((size_t)bh * N_ + i0) * D_;
    #pragma unroll
    for (int e = tid; e < 2048; e += 256) {
        int r = e >> 4, c = (e & 15) << 2;
        *reinterpret_cast<float4*>(Qsh + r * 68 + c) =
            *reinterpret_cast<const float4*>(qh + r * 64 + c);
        *reinterpret_cast<float4*>(Qsl + r * 68 + c) =
            *reinterpret_cast<const float4*>(ql + r * 64 + c);
    }
    __syncthreads();

    uint32_t qah[8][4], qal[8][4];
    #pragma unroll
    for (int kk = 0; kk < 8; kk++) {
        qah[kk][0] = __float_as_uint(Qsh[r0 * 68 + kk * 8 + l]);
        qah[kk][1] = __float_as_uint(Qsh[(r0 + 8) * 68 + kk * 8 + l]);
        qah[kk][2] = __float_as_uint(Qsh[r0 * 68 + kk * 8 + l + 4]);
        qah[kk][3] = __float_as_uint(Qsh[(r0 + 8) * 68 + kk * 8 + l + 4]);
        qal[kk][0] = __float_as_uint(Qsl[r0 * 68 + kk * 8 + l]);
        qal[kk][1] = __float_as_uint(Qsl[(r0 + 8) * 68 + kk * 8 + l]);
        qal[kk][2] = __float_as_uint(Qsl[r0 * 68 + kk * 8 + l + 4]);
        qal[kk][3] = __float_as_uint(Qsl[(r0 + 8) * 68 + kk * 8 + l + 4]);
    }

    const int i_lo = i0 + r0, i_hi = i_lo + 8;
    const float* blo = g_qr + (size_t)bh * N_ * N_ + (size_t)i_lo * N_;  // bias row i_lo
    const float* bhi = g_qr + (size_t)bh * N_ * N_ + (size_t)i_hi * N_;  // bias row i_hi

    float oacc[8][4] = {};
    float dp_lo = 0.0f, dp_hi = 0.0f;
    float* Ssh = Qsh;   // warp-private rows
    float* Ssl = Qsl;

    asm volatile("cp.async.wait_group 0;");
    __syncthreads();

    const int njt = 2 * it + 2;
    for (int jt = 0; jt < njt; jt++) {
        const int j0 = jt * 64;
        const int cur = jt & 1;
        // per-warp causal block limit: need j0+8n <= i_hi
        const int n_lim = max(0, min(8, ((i_hi - j0) >> 3) + 1));
        const bool full = (j0 + 63 <= i0);

        if (jt + 1 < njt) load_tile_async((jt + 1) * 64, cur ^ 1);
        asm volatile("cp.async.commit_group;");

        // hoisted bias gather: aligned float2, j-ascending
        float2 qv_lo[8], qv_hi[8];
        #pragma unroll
        for (int n = 0; n < 8; n++) {
            if (n < n_lim) {
                int jc = j0 + n * 8 + 2 * l;
                qv_lo[n] = *reinterpret_cast<const float2*>(blo + jc);
                qv_hi[n] = *reinterpret_cast<const float2*>(bhi + jc);
            }
        }

        const float* Kh = Khs + cur * 4352;
        const float* Kl = Kls + cur * 4352;
        const float* Vh = Vhs + cur * 4608;
        const float* Vl = Vls + cur * 4608;

        // GEMM1: S = Q . K^T  (3xTF32, split accumulators, ALU-free stream)
        float sacc[8][4] = {}, sac2[8][4] = {};
        #pragma unroll
        for (int kk = 0; kk < 8; kk++)
            #pragma unroll
            for (int n = 0; n < 8; n++) {
                if (n < n_lim) {
                    const int o0 = (n * 8 + g) * 68 + kk * 8 + l;
                    uint32_t bh0 = __float_as_uint(Kh[o0]);
                    uint32_t bh1 = __float_as_uint(Kh[o0 + 4]);
                    uint32_t bl0 = __float_as_uint(Kl[o0]);
                    uint32_t bl1 = __float_as_uint(Kl[o0 + 4]);
                    mma_tf32(sacc[n], qah[kk], bh0, bh1);
                    mma_tf32(sac2[n], qal[kk], bh0, bh1);
                    mma_tf32(sac2[n], qah[kk], bl0, bl1);
                }
            }

        // Epilogue: combine, +1, bias, mask, denom, split -> Ssh/Ssl
        #pragma unroll
        for (int n = 0; n < 8; n++) {
            if (n < n_lim) {
                int jc = j0 + n * 8 + 2 * l;
                float v00 = sacc[n][0] + sac2[n][0] + 1.0f + qv_lo[n].x;
                float v01 = sacc[n][1] + sac2[n][1] + 1.0f + qv_lo[n].y;
                float v10 = sacc[n][2] + sac2[n][2] + 1.0f + qv_hi[n].x;
                float v11 = sacc[n][3] + sac2[n][3] + 1.0f + qv_hi[n].y;
                if (!full) {
                    v00 = (jc     <= i_lo) ? v00 : 0.0f;
                    v01 = (jc + 1 <= i_lo) ? v01 : 0.0f;
                    v10 = (jc     <= i_hi) ? v10 : 0.0f;
                    v11 = (jc + 1 <= i_hi) ? v11 : 0.0f;
                }
                dp_lo += v00 + v01;
                dp_hi += v10 + v11;
                uint32_t h0, l0, h1, l1;
                split2(v00, h0, l0); split2(v01, h1, l1);
                *reinterpret_cast<float2*>(Ssh + r0 * 68 + n * 8 + 2 * l) =
                    make_float2(__uint_as_float(h0), __uint_as_float(h1));
                *reinterpret_cast<float2*>(Ssl + r0 * 68 + n * 8 + 2 * l) =
                    make_float2(__uint_as_float(l0), __uint_as_float(l1));
                split2(v10, h0, l0); split2(v11, h1, l1);
                *reinterpret_cast<float2*>(Ssh + (r0 + 8) * 68 + n * 8 + 2 * l) =
                    make_float2(__uint_as_float(h0), __uint_as_float(h1));
                *reinterpret_cast<float2*>(Ssl + (r0 + 8) * 68 + n * 8 + 2 * l) =
                    make_float2(__uint_as_float(l0), __uint_as_float(l1));
            }
        }
        __syncwarp();

        // GEMM2: O += S . V  (3xTF32, pre-split A from Ssh/Ssl, skip zero k)
        #pragma unroll
        for (int kk = 0; kk < 8; kk++) {
            if (kk < n_lim) {
                uint32_t ah[4], al[4];
                ah[0] = __float_as_uint(Ssh[r0 * 68 + kk * 8 + l]);
                ah[1] = __float_as_uint(Ssh[(r0 + 8) * 68 + kk * 8 + l]);
                ah[2] = __float_as_uint(Ssh[r0 * 68 + kk * 8 + l + 4]);
                ah[3] = __float_as_uint(Ssh[(r0 + 8) * 68 + kk * 8 + l + 4]);
                al[0] = __float_as_uint(Ssl[r0 * 68 + kk * 8 + l]);
                al[1] = __float_as_uint(Ssl[(r0 + 8) * 68 + kk * 8 + l]);
                al[2] = __float_as_uint(Ssl[r0 * 68 + kk * 8 + l + 4]);
                al[3] = __float_as_uint(Ssl[(r0 + 8) * 68 + kk * 8 + l + 4]);
                #pragma unroll
                for (int n = 0; n < 8; n++) {
                    const int p0 = (kk * 8 + l) * 72 + n * 8 + g;
                    const int p1 = (kk * 8 + l + 4) * 72 + n * 8 + g;
                    uint32_t bh0 = __float_as_uint(Vh[p0]);
                    uint32_t bh1 = __float_as_uint(Vh[p1]);
                    uint32_t bl0 = __float_as_uint(Vl[p0]);
                    uint32_t bl1 = __float_as_uint(Vl[p1]);
                    mma_tf32(oacc[n], ah, bh0, bh1);
                    mma_tf32(oacc[n], al, bh0, bh1);
                    mma_tf32(oacc[n], ah, bl0, bl1);
                }
            }
        }

        asm volatile("cp.async.wait_group 0;");
        __syncthreads();
    }

    // Row denominators: reduce across the 4 lanes of each quad
    dp_lo += __shfl_xor_sync(0xffffffffu, dp_lo, 1);
    dp_lo += __shfl_xor_sync(0xffffffffu, dp_lo, 2);
    dp_hi += __shfl_xor_sync(0xffffffffu, dp_hi, 1);
    dp_hi += __shfl_xor_sync(0xffffffffu, dp_hi, 2);
    const float rlo = 1.0f / dp_lo;
    const float rhi = 1.0f / dp_hi;

    float* olo = out + ((size_t)bh * N_ + i_lo) * D_;
    float* ohi = out + ((size_t)bh * N_ + i_hi) * D_;
    #pragma unroll
    for (int n = 0; n < 8; n++) {
        int dc = n * 8 + 2 * l;
        *reinterpret_cast<float2*>(olo + dc) =
            make_float2(oacc[n][0] * rlo, oacc[n][1] * rlo);
        *reinterpret_cast<float2*>(ohi + dc) =
            make_float2(oacc[n][2] * rhi, oacc[n][3] * rhi);
    }
}

// ---------------------------------------------------------------------------
extern "C" void kernel_launch(void* const* d_in, const int* in_sizes, int n_in,
                              void* d_out, int out_size) {
    const float* q   = (const float*)d_in[0];
    const float* k   = (const float*)d_in[1];
    const float* v   = (const float*)d_in[2];
    const float* dn  = (const float*)d_in[3];
    const float* rpe = (const float*)d_in[4];
    float* out = (float*)d_out;

    prep_norm_kernel<<<(2 * BH_ * N_) / 8, 256>>>(q, k);
    prep_v_kernel<<<(BH_ * N_ * D_ / 4) / 256, 256>>>(v, dn);

    const int qr_smem = (2 * 8704 + 2 * 4352) * sizeof(float);      // 104448 B
    cudaFuncSetAttribute(qr_mma_kernel,
                         cudaFuncAttributeMaxDynamicSharedMemorySize, qr_smem);
    qr_mma_kernel<<<dim3(16, 8, BH_), 256, qr_smem>>>(rpe);

    const int mn_smem = 53248 * sizeof(float);                      // 212992 B
    cudaFuncSetAttribute(fastmax_mma_kernel,
                         cudaFuncAttributeMaxDynamicSharedMemorySize, mn_smem);
    fastmax_mma_kernel<<<dim3(8, BH_), 256, mn_smem>>>(out);
}

// round 9
// speedup vs baseline: 1.4312x; 1.4312x over previous
#include <cuda_runtime.h>
#include <cstdint>

// fastmax attention, b=4 h=16 n=1024 d=64.
// Round 8: R6 structure (proven 350.7us) + ONE change: S pre-split in the
// epilogue (Ssh/Ssl) so GEMM2's mma stream is pure LDS+HMMA (no split2 ALU).
//   prep:   Qn = q/||q|| (fp32); K,V pre-split to tf32 hi/lo pairs
//   qr:     QR[bh][i][m] = Qn_i . rpe2[m]
//   main:   S = 1 + Qn Kn^T + QR[i][i-j]  (j<=i),  out = S Vp / rowsum(S)

#define B_  4
#define H_  16
#define N_  1024
#define D_  64
#define BH_ (B_*H_)

__device__ float g_qn [(size_t)BH_ * N_ * D_];          // fp32 normalized q
__device__ float g_knh[(size_t)BH_ * N_ * D_];          // tf32-hi of normalized k
__device__ float g_knl[(size_t)BH_ * N_ * D_];          // tf32-lo
__device__ float g_vph[(size_t)BH_ * N_ * D_];          // tf32-hi of v+0.1*noise
__device__ float g_vpl[(size_t)BH_ * N_ * D_];          // tf32-lo
__device__ float g_qr [(size_t)BH_ * N_ * N_];          // fp32 bias table (m-indexed)

// ---------------------------------------------------------------------------
__device__ __forceinline__ void split2(float x, uint32_t& hi, uint32_t& lo) {
    asm("cvt.rna.tf32.f32 %0, %1;" : "=r"(hi) : "f"(x));
    float r = x - __uint_as_float(hi);
    asm("cvt.rna.tf32.f32 %0, %1;" : "=r"(lo) : "f"(r));
}

__device__ __forceinline__ void mma_tf32(float c[4], const uint32_t a[4],
                                         uint32_t b0, uint32_t b1) {
    asm("mma.sync.aligned.m16n8k8.row.col.f32.tf32.tf32.f32 "
        "{%0,%1,%2,%3}, {%4,%5,%6,%7}, {%8,%9}, {%0,%1,%2,%3};"
        : "+f"(c[0]), "+f"(c[1]), "+f"(c[2]), "+f"(c[3])
        : "r"(a[0]), "r"(a[1]), "r"(a[2]), "r"(a[3]), "r"(b0), "r"(b1));
}

// 3xTF32 with full-fp32 B split on load (qr kernel only)
__device__ __forceinline__ void mma3(float c[4],
                                     const uint32_t ah[4], const uint32_t al[4],
                                     float b0f, float b1f) {
    uint32_t bh0, bl0, bh1, bl1;
    split2(b0f, bh0, bl0);
    split2(b1f, bh1, bl1);
    mma_tf32(c, ah, bh0, bh1);
    mma_tf32(c, al, bh0, bh1);
    mma_tf32(c, ah, bl0, bl1);
}

__device__ __forceinline__ void cp_async16(void* sdst, const void* gsrc) {
    uint32_t s = (uint32_t)__cvta_generic_to_shared(sdst);
    asm volatile("cp.async.cg.shared.global [%0], [%1], 16;" :: "r"(s), "l"(gsrc));
}

// ---------------------------------------------------------------------------
// prep: normalize q -> g_qn (fp32); normalize k -> split tf32 hi/lo
// ---------------------------------------------------------------------------
__global__ void prep_norm_kernel(const float* __restrict__ q,
                                 const float* __restrict__ k) {
    int gw   = (blockIdx.x * blockDim.x + threadIdx.x) >> 5;
    int lane = threadIdx.x & 31;
    const int total = BH_ * N_;
    const bool is_q = (gw < total);
    const int row = is_q ? gw : gw - total;
    const float* src = is_q ? q : k;
    const float2 v = reinterpret_cast<const float2*>(src + (size_t)row * D_)[lane];
    float ss = v.x * v.x + v.y * v.y;
    #pragma unroll
    for (int o = 16; o > 0; o >>= 1) ss += __shfl_xor_sync(0xffffffffu, ss, o);
    float inv = rsqrtf(ss);
    float x = v.x * inv, y = v.y * inv;
    if (is_q) {
        reinterpret_cast<float2*>(g_qn + (size_t)row * D_)[lane] = make_float2(x, y);
    } else {
        uint32_t xh, xl, yh, yl;
        split2(x, xh, xl);
        split2(y, yh, yl);
        reinterpret_cast<float2*>(g_knh + (size_t)row * D_)[lane] =
            make_float2(__uint_as_float(xh), __uint_as_float(yh));
        reinterpret_cast<float2*>(g_knl + (size_t)row * D_)[lane] =
            make_float2(__uint_as_float(xl), __uint_as_float(yl));
    }
}

// ---------------------------------------------------------------------------
// prep: Vp = v + 0.1*noise -> split tf32 hi/lo
// ---------------------------------------------------------------------------
__global__ void prep_v_kernel(const float* __restrict__ v,
                              const float* __restrict__ nz) {
    int i = blockIdx.x * blockDim.x + threadIdx.x;
    float4 a = reinterpret_cast<const float4*>(v)[i];
    float4 b = reinterpret_cast<const float4*>(nz)[i];
    float4 h, l;
    uint32_t th, tl;
    split2(fmaf(0.1f, b.x, a.x), th, tl); h.x = __uint_as_float(th); l.x = __uint_as_float(tl);
    split2(fmaf(0.1f, b.y, a.y), th, tl); h.y = __uint_as_float(th); l.y = __uint_as_float(tl);
    split2(fmaf(0.1f, b.z, a.z), th, tl); h.z = __uint_as_float(th); l.z = __uint_as_float(tl);
    split2(fmaf(0.1f, b.w, a.w), th, tl); h.w = __uint_as_float(th); l.w = __uint_as_float(tl);
    reinterpret_cast<float4*>(g_vph)[i] = h;
    reinterpret_cast<float4*>(g_vpl)[i] = l;
}

// ---------------------------------------------------------------------------
// QR[bh][i][m] = Qn_i . rpe2[m], 128x64 tiles via 3xTF32 mma.  (R6 version)
// ---------------------------------------------------------------------------
__global__ void __launch_bounds__(256) qr_mma_kernel(const float* __restrict__ rpe) {
    const int mx = blockIdx.x, iy = blockIdx.y, bh = blockIdx.z;
    if (mx > 2 * iy + 1) return;

    extern __shared__ float sm[];
    float* Qs = sm;              // [128][68]
    float* Rs = sm + 128 * 68;   // [64][68]

    const int tid = threadIdx.x;
    const int w = tid >> 5, lane = tid & 31;
    const int g = lane >> 2, l = lane & 3;
    const int i0 = iy * 128, m0 = mx * 64;

    const float* qsrc = g_qn + ((size_t)bh * N_ + i0) * D_;
    #pragma unroll
    for (int e = tid; e < 2048; e += 256) {
        int r = e >> 4, c = (e & 15) << 2;
        *reinterpret_cast<float4*>(Qs + r * 68 + c) =
            *reinterpret_cast<const float4*>(qsrc + r * 64 + c);
    }
    const float* rsrc = rpe + (size_t)(N_ - 1 + m0) * D_;
    #pragma unroll
    for (int e = tid; e < 1024; e += 256) {
        int r = e >> 4, c = (e & 15) << 2;
        *reinterpret_cast<float4*>(Rs + r * 68 + c) =
            *reinterpret_cast<const float4*>(rsrc + r * 64 + c);
    }
    __syncthreads();

    const int r0 = w * 16 + g;
    float acc[8][4] = {};
    #pragma unroll
    for (int kk = 0; kk < 8; kk++) {
        uint32_t ah[4], al[4];
        split2(Qs[r0 * 68 + kk * 8 + l],           ah[0], al[0]);
        split2(Qs[(r0 + 8) * 68 + kk * 8 + l],     ah[1], al[1]);
        split2(Qs[r0 * 68 + kk * 8 + l + 4],       ah[2], al[2]);
        split2(Qs[(r0 + 8) * 68 + kk * 8 + l + 4], ah[3], al[3]);
        #pragma unroll
        for (int n = 0; n < 8; n++) {
            float b0 = Rs[(n * 8 + g) * 68 + kk * 8 + l];
            float b1 = Rs[(n * 8 + g) * 68 + kk * 8 + l + 4];
            mma3(acc[n], ah, al, b0, b1);
        }
    }

    float* dst = g_qr + (size_t)bh * N_ * N_;
    const int i_lo = i0 + r0, i_hi = i_lo + 8;
    #pragma unroll
    for (int n = 0; n < 8; n++) {
        int mc = m0 + n * 8 + 2 * l;
        *reinterpret_cast<float2*>(dst + (size_t)i_lo * N_ + mc) =
            make_float2(acc[n][0], acc[n][1]);
        *reinterpret_cast<float2*>(dst + (size_t)i_hi * N_ + mc) =
            make_float2(acc[n][2], acc[n][3]);
    }
}

// ---------------------------------------------------------------------------
// Main fused attention: block = (bh, 128-row i-tile), 8 warps.
// Double-buffered cp.async K/V (pre-split hi/lo), hoisted bias gather,
// S pre-split in epilogue -> GEMM2 is pure LDS+HMMA.
// ---------------------------------------------------------------------------
__global__ void __launch_bounds__(256) fastmax_mma_kernel(float* __restrict__ out) {
    extern __shared__ float sm[];
    float* Qs  = sm;                 // [128][68], reused as Ssh after Q extract
    float* Ssl = sm + 8704;          // [128][68], lo half of staged S
    float* Khs = sm + 17408;         // 2 x [64][68]
    float* Kls = sm + 26112;         // 2 x [64][68]
    float* Vhs = sm + 34816;         // 2 x [64][72]
    float* Vls = sm + 44032;         // 2 x [64][72]

    const int it = 7 - blockIdx.x;   // heavy tiles first
    const int bh = blockIdx.y;
    const int i0 = it * 128;

    const int tid = threadIdx.x;
    const int w = tid >> 5, lane = tid & 31;
    const int g = lane >> 2, l = lane & 3;
    const int r0 = w * 16 + g;

    auto load_tile_async = [&](int j0, int buf) {
        const size_t base = ((size_t)bh * N_ + j0) * D_;
        const float* kh = g_knh + base;
        const float* kl = g_knl + base;
        const float* vh = g_vph + base;
        const float* vl = g_vpl + base;
        float* Kh = Khs + buf * 4352;
        float* Kl = Kls + buf * 4352;
        float* Vh = Vhs + buf * 4608;
        float* Vl = Vls + buf * 4608;
        #pragma unroll
        for (int e = tid; e < 1024; e += 256) {
            int r = e >> 4, c = (e & 15) << 2;
            cp_async16(Kh + r * 68 + c, kh + r * 64 + c);
            cp_async16(Kl + r * 68 + c, kl + r * 64 + c);
            cp_async16(Vh + r * 72 + c, vh + r * 64 + c);
            cp_async16(Vl + r * 72 + c, vl + r * 64 + c);
        }
    };

    // Load Q tile, extract per-warp A fragments, pre-split hi/lo
    const float* qsrc = g_qn + ((size_t)bh * N_ + i0) * D_;
    #pragma unroll
    for (int e = tid; e < 2048; e += 256) {
        int r = e >> 4, c = (e & 15) << 2;
        *reinterpret_cast<float4*>(Qs + r * 68 + c) =
            *reinterpret_cast<const float4*>(qsrc + r * 64 + c);
    }
    // kick off K/V preload for tile 0 while Q settles
    load_tile_async(0, 0);
    asm volatile("cp.async.commit_group;");
    __syncthreads();

    uint32_t qah[8][4], qal[8][4];
    #pragma unroll
    for (int kk = 0; kk < 8; kk++) {
        split2(Qs[r0 * 68 + kk * 8 + l],           qah[kk][0], qal[kk][0]);
        split2(Qs[(r0 + 8) * 68 + kk * 8 + l],     qah[kk][1], qal[kk][1]);
        split2(Qs[r0 * 68 + kk * 8 + l + 4],       qah[kk][2], qal[kk][2]);
        split2(Qs[(r0 + 8) * 68 + kk * 8 + l + 4], qah[kk][3], qal[kk][3]);
    }

    const int i_lo = i0 + r0, i_hi = i_lo + 8;
    const float* qlo = g_qr + (size_t)bh * N_ * N_ + (size_t)i_lo * (N_ + 1);
    const float* qhi = g_qr + (size_t)bh * N_ * N_ + (size_t)i_hi * (N_ + 1);

    float oacc[8][4] = {};
    float dp_lo = 0.0f, dp_hi = 0.0f;
    float* Ssh = Qs;   // warp-private rows

    asm volatile("cp.async.wait_group 0;");
    __syncthreads();

    const int njt = 2 * it + 2;
    for (int jt = 0; jt < njt; jt++) {
        const int j0 = jt * 64;
        const int cur = jt & 1;

        // issue next tile's copies (overlap with this tile's compute)
        if (jt + 1 < njt) load_tile_async((jt + 1) * 64, cur ^ 1);
        asm volatile("cp.async.commit_group;");

        // hoisted bias gather (completes under GEMM1)
        const bool full = (j0 + 63 <= i0);
        float qrv[8][4];
        #pragma unroll
        for (int n = 0; n < 8; n++) {
            int jc = j0 + n * 8 + 2 * l;
            if (full) {
                qrv[n][0] = __ldg(qlo - jc);
                qrv[n][1] = __ldg(qlo - (jc + 1));
                qrv[n][2] = __ldg(qhi - jc);
                qrv[n][3] = __ldg(qhi - (jc + 1));
            } else {
                qrv[n][0] = (jc     <= i_lo) ? __ldg(qlo - jc)       : 0.0f;
                qrv[n][1] = (jc + 1 <= i_lo) ? __ldg(qlo - (jc + 1)) : 0.0f;
                qrv[n][2] = (jc     <= i_hi) ? __ldg(qhi - jc)       : 0.0f;
                qrv[n][3] = (jc + 1 <= i_hi) ? __ldg(qhi - (jc + 1)) : 0.0f;
            }
        }

        const float* Kh = Khs + cur * 4352;
        const float* Kl = Kls + cur * 4352;
        const float* Vh = Vhs + cur * 4608;
        const float* Vl = Vls + cur * 4608;

        // GEMM1: S = Q . K^T  (3xTF32, K pre-split, pure LDS+HMMA)
        float sacc[8][4] = {};
        #pragma unroll
        for (int kk = 0; kk < 8; kk++)
            #pragma unroll
            for (int n = 0; n < 8; n++) {
                const int o0 = (n * 8 + g) * 68 + kk * 8 + l;
                uint32_t bh0 = __float_as_uint(Kh[o0]);
                uint32_t bh1 = __float_as_uint(Kh[o0 + 4]);
                uint32_t bl0 = __float_as_uint(Kl[o0]);
                uint32_t bl1 = __float_as_uint(Kl[o0 + 4]);
                mma_tf32(sacc[n], qah[kk], bh0, bh1);
                mma_tf32(sacc[n], qal[kk], bh0, bh1);
                mma_tf32(sacc[n], qah[kk], bl0, bl1);
            }

        // Epilogue: +1, bias, causal mask, denom partials, SPLIT S -> Ssh/Ssl
        #pragma unroll
        for (int n = 0; n < 8; n++) {
            int jc = j0 + n * 8 + 2 * l;
            float v00, v01, v10, v11;
            if (full) {
                v00 = sacc[n][0] + 1.0f + qrv[n][0];
                v01 = sacc[n][1] + 1.0f + qrv[n][1];
                v10 = sacc[n][2] + 1.0f + qrv[n][2];
                v11 = sacc[n][3] + 1.0f + qrv[n][3];
            } else {
                v00 = (jc     <= i_lo) ? sacc[n][0] + 1.0f + qrv[n][0] : 0.0f;
                v01 = (jc + 1 <= i_lo) ? sacc[n][1] + 1.0f + qrv[n][1] : 0.0f;
                v10 = (jc     <= i_hi) ? sacc[n][2] + 1.0f + qrv[n][2] : 0.0f;
                v11 = (jc + 1 <= i_hi) ? sacc[n][3] + 1.0f + qrv[n][3] : 0.0f;
            }
            dp_lo += v00 + v01;
            dp_hi += v10 + v11;
            uint32_t h0, l0, h1, l1;
            split2(v00, h0, l0); split2(v01, h1, l1);
            *reinterpret_cast<float2*>(Ssh + r0 * 68 + n * 8 + 2 * l) =
                make_float2(__uint_as_float(h0), __uint_as_float(h1));
            *reinterpret_cast<float2*>(Ssl + r0 * 68 + n * 8 + 2 * l) =
                make_float2(__uint_as_float(l0), __uint_as_float(l1));
            split2(v10, h0, l0); split2(v11, h1, l1);
            *reinterpret_cast<float2*>(Ssh + (r0 + 8) * 68 + n * 8 + 2 * l) =
                make_float2(__uint_as_float(h0), __uint_as_float(h1));
            *reinterpret_cast<float2*>(Ssl + (r0 + 8) * 68 + n * 8 + 2 * l) =
                make_float2(__uint_as_float(l0), __uint_as_float(l1));
        }
        __syncwarp();

        // GEMM2: O += S . V  (3xTF32, A pre-split in smem, pure LDS+HMMA)
        #pragma unroll
        for (int kk = 0; kk < 8; kk++) {
            uint32_t ah[4], al[4];
            ah[0] = __float_as_uint(Ssh[r0 * 68 + kk * 8 + l]);
            ah[1] = __float_as_uint(Ssh[(r0 + 8) * 68 + kk * 8 + l]);
            ah[2] = __float_as_uint(Ssh[r0 * 68 + kk * 8 + l + 4]);
            ah[3] = __float_as_uint(Ssh[(r0 + 8) * 68 + kk * 8 + l + 4]);
            al[0] = __float_as_uint(Ssl[r0 * 68 + kk * 8 + l]);
            al[1] = __float_as_uint(Ssl[(r0 + 8) * 68 + kk * 8 + l]);
            al[2] = __float_as_uint(Ssl[r0 * 68 + kk * 8 + l + 4]);
            al[3] = __float_as_uint(Ssl[(r0 + 8) * 68 + kk * 8 + l + 4]);
            #pragma unroll
            for (int n = 0; n < 8; n++) {
                const int p0 = (kk * 8 + l) * 72 + n * 8 + g;
                const int p1 = (kk * 8 + l + 4) * 72 + n * 8 + g;
                uint32_t bh0 = __float_as_uint(Vh[p0]);
                uint32_t bh1 = __float_as_uint(Vh[p1]);
                uint32_t bl0 = __float_as_uint(Vl[p0]);
                uint32_t bl1 = __float_as_uint(Vl[p1]);
                mma_tf32(oacc[n], ah, bh0, bh1);
                mma_tf32(oacc[n], al, bh0, bh1);
                mma_tf32(oacc[n], ah, bl0, bl1);
            }
        }

        // next buffer ready + all warps done reading current buffers
        asm volatile("cp.async.wait_group 0;");
        __syncthreads();
    }

    // Row denominators: reduce across the 4 lanes of each quad
    dp_lo += __shfl_xor_sync(0xffffffffu, dp_lo, 1);
    dp_lo += __shfl_xor_sync(0xffffffffu, dp_lo, 2);
    dp_hi += __shfl_xor_sync(0xffffffffu, dp_hi, 1);
    dp_hi += __shfl_xor_sync(0xffffffffu, dp_hi, 2);
    const float rlo = 1.0f / dp_lo;
    const float rhi = 1.0f / dp_hi;

    float* olo = out + ((size_t)bh * N_ + i_lo) * D_;
    float* ohi = out + ((size_t)bh * N_ + i_hi) * D_;
    #pragma unroll
    for (int n = 0; n < 8; n++) {
        int dc = n * 8 + 2 * l;
        *reinterpret_cast<float2*>(olo + dc) =
            make_float2(oacc[n][0] * rlo, oacc[n][1] * rlo);
        *reinterpret_cast<float2*>(ohi + dc) =
            make_float2(oacc[n][2] * rhi, oacc[n][3] * rhi);
    }
}

// ---------------------------------------------------------------------------
extern "C" void kernel_launch(void* const* d_in, const int* in_sizes, int n_in,
                              void* d_out, int out_size) {
    const float* q   = (const float*)d_in[0];
    const float* k   = (const float*)d_in[1];
    const float* v   = (const float*)d_in[2];
    const float* dn  = (const float*)d_in[3];
    const float* rpe = (const float*)d_in[4];
    float* out = (float*)d_out;

    prep_norm_kernel<<<(2 * BH_ * N_) / 8, 256>>>(q, k);
    prep_v_kernel<<<(BH_ * N_ * D_ / 4) / 256, 256>>>(v, dn);

    const int qr_smem = (128 * 68 + 64 * 68) * sizeof(float);       // 52224 B
    cudaFuncSetAttribute(qr_mma_kernel,
                         cudaFuncAttributeMaxDynamicSharedMemorySize, qr_smem);
    qr_mma_kernel<<<dim3(16, 8, BH_), 256, qr_smem>>>(rpe);

    const int mn_smem = 53248 * sizeof(float);                      // 212992 B
    cudaFuncSetAttribute(fastmax_mma_kernel,
                         cudaFuncAttributeMaxDynamicSharedMemorySize, mn_smem);
    fastmax_mma_kernel<<<dim3(8, BH_), 256, mn_smem>>>(out);
}

// round 11
// speedup vs baseline: 1.7088x; 1.1939x over previous
#include <cuda_runtime.h>
#include <cstdint>

// fastmax attention, b=4 h=16 n=1024 d=64.
// Round 10: R6 arithmetic (3xTF32 mma, pre-split K/V, ALU-free GEMM1) at
// 128 threads / 64-row i-tiles / single-buffered smem -> 2 CTAs per SM.
//   prep:   Qn = q/||q|| (fp32); K,V pre-split to tf32 hi/lo pairs
//   qr:     QR[bh][i][m] = Qn_i . rpe2[m]
//   main:   S = 1 + Qn Kn^T + QR[i][i-j]  (j<=i),  out = S Vp / rowsum(S)

#define B_  4
#define H_  16
#define N_  1024
#define D_  64
#define BH_ (B_*H_)

__device__ float g_qn [(size_t)BH_ * N_ * D_];          // fp32 normalized q
__device__ float g_knh[(size_t)BH_ * N_ * D_];          // tf32-hi of normalized k
__device__ float g_knl[(size_t)BH_ * N_ * D_];          // tf32-lo
__device__ float g_vph[(size_t)BH_ * N_ * D_];          // tf32-hi of v+0.1*noise
__device__ float g_vpl[(size_t)BH_ * N_ * D_];          // tf32-lo
__device__ float g_qr [(size_t)BH_ * N_ * N_];          // fp32 bias table (m-indexed)

// ---------------------------------------------------------------------------
__device__ __forceinline__ void split2(float x, uint32_t& hi, uint32_t& lo) {
    asm("cvt.rna.tf32.f32 %0, %1;" : "=r"(hi) : "f"(x));
    float r = x - __uint_as_float(hi);
    asm("cvt.rna.tf32.f32 %0, %1;" : "=r"(lo) : "f"(r));
}

__device__ __forceinline__ void mma_tf32(float c[4], const uint32_t a[4],
                                         uint32_t b0, uint32_t b1) {
    asm("mma.sync.aligned.m16n8k8.row.col.f32.tf32.tf32.f32 "
        "{%0,%1,%2,%3}, {%4,%5,%6,%7}, {%8,%9}, {%0,%1,%2,%3};"
        : "+f"(c[0]), "+f"(c[1]), "+f"(c[2]), "+f"(c[3])
        : "r"(a[0]), "r"(a[1]), "r"(a[2]), "r"(a[3]), "r"(b0), "r"(b1));
}

// 3xTF32 with full-fp32 B split on load (qr kernel + GEMM2 A-splits)
__device__ __forceinline__ void mma3(float c[4],
                                     const uint32_t ah[4], const uint32_t al[4],
                                     float b0f, float b1f) {
    uint32_t bh0, bl0, bh1, bl1;
    split2(b0f, bh0, bl0);
    split2(b1f, bh1, bl1);
    mma_tf32(c, ah, bh0, bh1);
    mma_tf32(c, al, bh0, bh1);
    mma_tf32(c, ah, bl0, bl1);
}

__device__ __forceinline__ void cp_async16(void* sdst, const void* gsrc) {
    uint32_t s = (uint32_t)__cvta_generic_to_shared(sdst);
    asm volatile("cp.async.cg.shared.global [%0], [%1], 16;" :: "r"(s), "l"(gsrc));
}

// ---------------------------------------------------------------------------
// prep: normalize q -> g_qn (fp32); normalize k -> split tf32 hi/lo
// ---------------------------------------------------------------------------
__global__ void prep_norm_kernel(const float* __restrict__ q,
                                 const float* __restrict__ k) {
    int gw   = (blockIdx.x * blockDim.x + threadIdx.x) >> 5;
    int lane = threadIdx.x & 31;
    const int total = BH_ * N_;
    const bool is_q = (gw < total);
    const int row = is_q ? gw : gw - total;
    const float* src = is_q ? q : k;
    const float2 v = reinterpret_cast<const float2*>(src + (size_t)row * D_)[lane];
    float ss = v.x * v.x + v.y * v.y;
    #pragma unroll
    for (int o = 16; o > 0; o >>= 1) ss += __shfl_xor_sync(0xffffffffu, ss, o);
    float inv = rsqrtf(ss);
    float x = v.x * inv, y = v.y * inv;
    if (is_q) {
        reinterpret_cast<float2*>(g_qn + (size_t)row * D_)[lane] = make_float2(x, y);
    } else {
        uint32_t xh, xl, yh, yl;
        split2(x, xh, xl);
        split2(y, yh, yl);
        reinterpret_cast<float2*>(g_knh + (size_t)row * D_)[lane] =
            make_float2(__uint_as_float(xh), __uint_as_float(yh));
        reinterpret_cast<float2*>(g_knl + (size_t)row * D_)[lane] =
            make_float2(__uint_as_float(xl), __uint_as_float(yl));
    }
}

// ---------------------------------------------------------------------------
// prep: Vp = v + 0.1*noise -> split tf32 hi/lo
// ---------------------------------------------------------------------------
__global__ void prep_v_kernel(const float* __restrict__ v,
                              const float* __restrict__ nz) {
    int i = blockIdx.x * blockDim.x + threadIdx.x;
    float4 a = reinterpret_cast<const float4*>(v)[i];
    float4 b = reinterpret_cast<const float4*>(nz)[i];
    float4 h, l;
    uint32_t th, tl;
    split2(fmaf(0.1f, b.x, a.x), th, tl); h.x = __uint_as_float(th); l.x = __uint_as_float(tl);
    split2(fmaf(0.1f, b.y, a.y), th, tl); h.y = __uint_as_float(th); l.y = __uint_as_float(tl);
    split2(fmaf(0.1f, b.z, a.z), th, tl); h.z = __uint_as_float(th); l.z = __uint_as_float(tl);
    split2(fmaf(0.1f, b.w, a.w), th, tl); h.w = __uint_as_float(th); l.w = __uint_as_float(tl);
    reinterpret_cast<float4*>(g_vph)[i] = h;
    reinterpret_cast<float4*>(g_vpl)[i] = l;
}

// ---------------------------------------------------------------------------
// QR[bh][i][m] = Qn_i . rpe2[m], 128x64 tiles via 3xTF32 mma.  (R6 version)
// ---------------------------------------------------------------------------
__global__ void __launch_bounds__(256) qr_mma_kernel(const float* __restrict__ rpe) {
    const int mx = blockIdx.x, iy = blockIdx.y, bh = blockIdx.z;
    if (mx > 2 * iy + 1) return;

    extern __shared__ float sm[];
    float* Qs = sm;              // [128][68]
    float* Rs = sm + 128 * 68;   // [64][68]

    const int tid = threadIdx.x;
    const int w = tid >> 5, lane = tid & 31;
    const int g = lane >> 2, l = lane & 3;
    const int i0 = iy * 128, m0 = mx * 64;

    const float* qsrc = g_qn + ((size_t)bh * N_ + i0) * D_;
    #pragma unroll
    for (int e = tid; e < 2048; e += 256) {
        int r = e >> 4, c = (e & 15) << 2;
        *reinterpret_cast<float4*>(Qs + r * 68 + c) =
            *reinterpret_cast<const float4*>(qsrc + r * 64 + c);
    }
    const float* rsrc = rpe + (size_t)(N_ - 1 + m0) * D_;
    #pragma unroll
    for (int e = tid; e < 1024; e += 256) {
        int r = e >> 4, c = (e & 15) << 2;
        *reinterpret_cast<float4*>(Rs + r * 68 + c) =
            *reinterpret_cast<const float4*>(rsrc + r * 64 + c);
    }
    __syncthreads();

    const int r0 = w * 16 + g;
    float acc[8][4] = {};
    #pragma unroll
    for (int kk = 0; kk < 8; kk++) {
        uint32_t ah[4], al[4];
        split2(Qs[r0 * 68 + kk * 8 + l],           ah[0], al[0]);
        split2(Qs[(r0 + 8) * 68 + kk * 8 + l],     ah[1], al[1]);
        split2(Qs[r0 * 68 + kk * 8 + l + 4],       ah[2], al[2]);
        split2(Qs[(r0 + 8) * 68 + kk * 8 + l + 4], ah[3], al[3]);
        #pragma unroll
        for (int n = 0; n < 8; n++) {
            float b0 = Rs[(n * 8 + g) * 68 + kk * 8 + l];
            float b1 = Rs[(n * 8 + g) * 68 + kk * 8 + l + 4];
            mma3(acc[n], ah, al, b0, b1);
        }
    }

    float* dst = g_qr + (size_t)bh * N_ * N_;
    const int i_lo = i0 + r0, i_hi = i_lo + 8;
    #pragma unroll
    for (int n = 0; n < 8; n++) {
        int mc = m0 + n * 8 + 2 * l;
        *reinterpret_cast<float2*>(dst + (size_t)i_lo * N_ + mc) =
            make_float2(acc[n][0], acc[n][1]);
        *reinterpret_cast<float2*>(dst + (size_t)i_hi * N_ + mc) =
            make_float2(acc[n][2], acc[n][3]);
    }
}

// ---------------------------------------------------------------------------
// Main fused attention: block = (bh, 64-row i-tile), 4 warps, 2 CTAs/SM.
// Single-buffered cp.async K/V (pre-split hi/lo); cross-CTA overlap hides
// the load phase. GEMM loops identical to the proven R6 streams.
// ---------------------------------------------------------------------------
__global__ void __launch_bounds__(128, 2) fastmax_mma_kernel(float* __restrict__ out) {
    extern __shared__ float sm[];
    float* Qs = sm;                  // [64][68], reused as Ss after Q extract
    float* Kh = sm + 4352;           // [64][68]
    float* Kl = sm + 8704;           // [64][68]
    float* Vh = sm + 13056;          // [64][72]
    float* Vl = sm + 17664;          // [64][72]  total 22272 floats = 89088 B

    const int it = 15 - blockIdx.x;  // heavy tiles first
    const int bh = blockIdx.y;
    const int i0 = it * 64;

    const int tid = threadIdx.x;
    const int w = tid >> 5, lane = tid & 31;
    const int g = lane >> 2, l = lane & 3;
    const int r0 = w * 16 + g;

    // Load Q strip (64 rows), extract per-warp A fragments, pre-split hi/lo
    const float* qsrc = g_qn + ((size_t)bh * N_ + i0) * D_;
    #pragma unroll
    for (int e = tid; e < 1024; e += 128) {
        int r = e >> 4, c = (e & 15) << 2;
        *reinterpret_cast<float4*>(Qs + r * 68 + c) =
            *reinterpret_cast<const float4*>(qsrc + r * 64 + c);
    }
    __syncthreads();

    uint32_t qah[8][4], qal[8][4];
    #pragma unroll
    for (int kk = 0; kk < 8; kk++) {
        split2(Qs[r0 * 68 + kk * 8 + l],           qah[kk][0], qal[kk][0]);
        split2(Qs[(r0 + 8) * 68 + kk * 8 + l],     qah[kk][1], qal[kk][1]);
        split2(Qs[r0 * 68 + kk * 8 + l + 4],       qah[kk][2], qal[kk][2]);
        split2(Qs[(r0 + 8) * 68 + kk * 8 + l + 4], qah[kk][3], qal[kk][3]);
    }

    const int i_lo = i0 + r0, i_hi = i_lo + 8;
    const float* qlo = g_qr + (size_t)bh * N_ * N_ + (size_t)i_lo * (N_ + 1);
    const float* qhi = g_qr + (size_t)bh * N_ * N_ + (size_t)i_hi * (N_ + 1);

    float oacc[8][4] = {};
    float dp_lo = 0.0f, dp_hi = 0.0f;
    float* Ss = Qs;   // warp-private rows -> __syncwarp suffices

    __syncthreads();  // Q fragment extraction done before Ss reuse

    const int njt = it + 1;
    for (int jt = 0; jt < njt; jt++) {
        const int j0 = jt * 64;

        // issue this tile's K/V copies into the single buffer
        {
            const size_t base = ((size_t)bh * N_ + j0) * D_;
            const float* kh = g_knh + base;
            const float* kl = g_knl + base;
            const float* vh = g_vph + base;
            const float* vl = g_vpl + base;
            #pragma unroll
            for (int e = tid; e < 1024; e += 128) {
                int r = e >> 4, c = (e & 15) << 2;
                cp_async16(Kh + r * 68 + c, kh + r * 64 + c);
                cp_async16(Kl + r * 68 + c, kl + r * 64 + c);
                cp_async16(Vh + r * 72 + c, vh + r * 64 + c);
                cp_async16(Vl + r * 72 + c, vl + r * 64 + c);
            }
            asm volatile("cp.async.commit_group;");
        }

        // bias gather overlaps with the cp.async in flight
        const bool full = (jt < it);
        float qrv[8][4];
        #pragma unroll
        for (int n = 0; n < 8; n++) {
            int jc = j0 + n * 8 + 2 * l;
            if (full) {
                qrv[n][0] = __ldg(qlo - jc);
                qrv[n][1] = __ldg(qlo - (jc + 1));
                qrv[n][2] = __ldg(qhi - jc);
                qrv[n][3] = __ldg(qhi - (jc + 1));
            } else {
                qrv[n][0] = (jc     <= i_lo) ? __ldg(qlo - jc)       : 0.0f;
                qrv[n][1] = (jc + 1 <= i_lo) ? __ldg(qlo - (jc + 1)) : 0.0f;
                qrv[n][2] = (jc     <= i_hi) ? __ldg(qhi - jc)       : 0.0f;
                qrv[n][3] = (jc + 1 <= i_hi) ? __ldg(qhi - (jc + 1)) : 0.0f;
            }
        }

        asm volatile("cp.async.wait_group 0;");
        __syncthreads();

        // GEMM1: S = Q . K^T  (3xTF32, K pre-split, pure LDS+HMMA)
        float sacc[8][4] = {};
        #pragma unroll
        for (int kk = 0; kk < 8; kk++)
            #pragma unroll
            for (int n = 0; n < 8; n++) {
                const int o0 = (n * 8 + g) * 68 + kk * 8 + l;
                uint32_t bh0 = __float_as_uint(Kh[o0]);
                uint32_t bh1 = __float_as_uint(Kh[o0 + 4]);
                uint32_t bl0 = __float_as_uint(Kl[o0]);
                uint32_t bl1 = __float_as_uint(Kl[o0 + 4]);
                mma_tf32(sacc[n], qah[kk], bh0, bh1);
                mma_tf32(sacc[n], qal[kk], bh0, bh1);
                mma_tf32(sacc[n], qah[kk], bl0, bl1);
            }

        // Epilogue: +1, bias, causal mask, denom partials, stage fp32 S
        #pragma unroll
        for (int n = 0; n < 8; n++) {
            int jc = j0 + n * 8 + 2 * l;
            float v00, v01, v10, v11;
            if (full) {
                v00 = sacc[n][0] + 1.0f + qrv[n][0];
                v01 = sacc[n][1] + 1.0f + qrv[n][1];
                v10 = sacc[n][2] + 1.0f + qrv[n][2];
                v11 = sacc[n][3] + 1.0f + qrv[n][3];
            } else {
                v00 = (jc     <= i_lo) ? sacc[n][0] + 1.0f + qrv[n][0] : 0.0f;
                v01 = (jc + 1 <= i_lo) ? sacc[n][1] + 1.0f + qrv[n][1] : 0.0f;
                v10 = (jc     <= i_hi) ? sacc[n][2] + 1.0f + qrv[n][2] : 0.0f;
                v11 = (jc + 1 <= i_hi) ? sacc[n][3] + 1.0f + qrv[n][3] : 0.0f;
            }
            dp_lo += v00 + v01;
            dp_hi += v10 + v11;
            *reinterpret_cast<float2*>(Ss + r0 * 68 + n * 8 + 2 * l) =
                make_float2(v00, v01);
            *reinterpret_cast<float2*>(Ss + (r0 + 8) * 68 + n * 8 + 2 * l) =
                make_float2(v10, v11);
        }
        __syncwarp();

        // GEMM2: O += S . V  (3xTF32; A = S strip split on load, V pre-split)
        #pragma unroll
        for (int kk = 0; kk < 8; kk++) {
            uint32_t ah[4], al[4];
            split2(Ss[r0 * 68 + kk * 8 + l],           ah[0], al[0]);
            split2(Ss[(r0 + 8) * 68 + kk * 8 + l],     ah[1], al[1]);
            split2(Ss[r0 * 68 + kk * 8 + l + 4],       ah[2], al[2]);
            split2(Ss[(r0 + 8) * 68 + kk * 8 + l + 4], ah[3], al[3]);
            #pragma unroll
            for (int n = 0; n < 8; n++) {
                const int p0 = (kk * 8 + l) * 72 + n * 8 + g;
                const int p1 = (kk * 8 + l + 4) * 72 + n * 8 + g;
                uint32_t bh0 = __float_as_uint(Vh[p0]);
                uint32_t bh1 = __float_as_uint(Vh[p1]);
                uint32_t bl0 = __float_as_uint(Vl[p0]);
                uint32_t bl1 = __float_as_uint(Vl[p1]);
                mma_tf32(oacc[n], ah, bh0, bh1);
                mma_tf32(oacc[n], al, bh0, bh1);
                mma_tf32(oacc[n], ah, bl0, bl1);
            }
        }

        __syncthreads();   // all warps done reading K/V before next overwrite
    }

    // Row denominators: reduce across the 4 lanes of each quad
    dp_lo += __shfl_xor_sync(0xffffffffu, dp_lo, 1);
    dp_lo += __shfl_xor_sync(0xffffffffu, dp_lo, 2);
    dp_hi += __shfl_xor_sync(0xffffffffu, dp_hi, 1);
    dp_hi += __shfl_xor_sync(0xffffffffu, dp_hi, 2);
    const float rlo = 1.0f / dp_lo;
    const float rhi = 1.0f / dp_hi;

    float* olo = out + ((size_t)bh * N_ + i_lo) * D_;
    float* ohi = out + ((size_t)bh * N_ + i_hi) * D_;
    #pragma unroll
    for (int n = 0; n < 8; n++) {
        int dc = n * 8 + 2 * l;
        *reinterpret_cast<float2*>(olo + dc) =
            make_float2(oacc[n][0] * rlo, oacc[n][1] * rlo);
        *reinterpret_cast<float2*>(ohi + dc) =
            make_float2(oacc[n][2] * rhi, oacc[n][3] * rhi);
    }
}

// ---------------------------------------------------------------------------
extern "C" void kernel_launch(void* const* d_in, const int* in_sizes, int n_in,
                              void* d_out, int out_size) {
    const float* q   = (const float*)d_in[0];
    const float* k   = (const float*)d_in[1];
    const float* v   = (const float*)d_in[2];
    const float* dn  = (const float*)d_in[3];
    const float* rpe = (const float*)d_in[4];
    float* out = (float*)d_out;

    prep_norm_kernel<<<(2 * BH_ * N_) / 8, 256>>>(q, k);
    prep_v_kernel<<<(BH_ * N_ * D_ / 4) / 256, 256>>>(v, dn);

    const int qr_smem = (128 * 68 + 64 * 68) * sizeof(float);       // 52224 B
    cudaFuncSetAttribute(qr_mma_kernel,
                         cudaFuncAttributeMaxDynamicSharedMemorySize, qr_smem);
    qr_mma_kernel<<<dim3(16, 8, BH_), 256, qr_smem>>>(rpe);

    const int mn_smem = 22272 * sizeof(float);                      // 89088 B
    cudaFuncSetAttribute(fastmax_mma_kernel,
                         cudaFuncAttributeMaxDynamicSharedMemorySize, mn_smem);
    fastmax_mma_kernel<<<dim3(16, BH_), 128, mn_smem>>>(out);
}